// round 13
// baseline (speedup 1.0000x reference)
#include <cuda_runtime.h>
#include <cuda_fp16.h>
#include <stdint.h>

// ---------------------------------------------------------------------------
// GPRNet: out = sum_k temp[k] * A_hat^k (MLP(x)@W_fc) + b_fc  (scalar per node)
// 4 launches: fused MLP+hist, lookback scan (+finalize+seed), CSC scatter,
// persistent hop kernel. Hop kernel now runs as clusters of 2 with TMA
// MULTICAST cooperative-slice fills: each CTA bulk-loads HALF the fp16 curw
// array and multicasts it to both cluster CTAs -> per-hop L2 broadcast
// traffic halves (30MB -> 15MB). srow stores BYTE offsets (2*row) to drop a
// shift in the gather. Grid = 150 blocks (75 clusters) so residency (and the
// IVALL grid barrier) is safe under any die split. Node state in registers.
// ---------------------------------------------------------------------------

#define MAXN   100352
#define MAXE   3276800
#define NBLK   256
#define EBLK   256
#define SCANB  1024
#define MAXSB  128
#define PTHR   1024
#define SMEMB  (MAXN * 2)          // 200704 bytes fp16 curw
#define HALFB  (SMEMB / 2)         // 100352 bytes per multicast slice
#define SMEMT  (SMEMB + 16)        // + mbarrier slot

__device__ int      g_deg[MAXN];           // zero at every call entry (invariant)
__device__ int      g_off[MAXN + 1];
__device__ int      g_cursor[MAXN];
__device__ int      g_srow[MAXE];          // BYTE offsets (2*row)
__device__ float    g_dinv[MAXN];
__device__ float    g_s[MAXN];
__device__ float    g_hidden[MAXN];
__device__ float    g_curwA[MAXN];                       // fp32 self-term seed
__device__ __align__(16) __half g_hA[MAXN];              // fp16 ping
__device__ __align__(16) __half g_hB[MAXN];              // fp16 pong
__device__ unsigned g_barrier;
__device__ unsigned long long g_lb[MAXSB];               // lookback: flag<<32|val

// ---- fused per-node MLP + histogram -----------------------------------------
__global__ void __launch_bounds__(NBLK) k_mlp_hist(
    const float* __restrict__ x,
    const float* __restrict__ W1, const float* __restrict__ b1,
    const float* __restrict__ W2, const float* __restrict__ b2,
    const float* __restrict__ Wfc,
    const int* __restrict__ col,
    int N, int nbMlp, int E4, int rem)
{
    if ((int)blockIdx.x >= nbMlp) {
        int hb = blockIdx.x - nbMlp;
        if (hb == 0 && threadIdx.x < MAXSB) g_lb[threadIdx.x] = 0ull;  // reset lookback
        int t = hb * NBLK + threadIdx.x;
        if (t < E4) {
            int4 c4 = reinterpret_cast<const int4*>(col)[t];
            atomicAdd(&g_deg[c4.x], 1);
            atomicAdd(&g_deg[c4.y], 1);
            atomicAdd(&g_deg[c4.z], 1);
            atomicAdd(&g_deg[c4.w], 1);
        } else if (t - E4 < rem) {
            atomicAdd(&g_deg[col[4 * E4 + (t - E4)]], 1);
        }
        return;
    }

    __shared__ float sW1[32], sB1[32], sB2[64], sWfc[64];
    __shared__ __align__(16) float sW2[2048];

    for (int t = threadIdx.x; t < 2048; t += blockDim.x) sW2[t] = W2[t];
    if (threadIdx.x < 32) { sW1[threadIdx.x] = W1[threadIdx.x]; sB1[threadIdx.x] = b1[threadIdx.x]; }
    if (threadIdx.x < 64) { sB2[threadIdx.x] = b2[threadIdx.x]; sWfc[threadIdx.x] = Wfc[threadIdx.x]; }
    __syncthreads();

    int i = blockIdx.x * blockDim.x + threadIdx.x;
    if (i >= N) return;
    if (i == 0) g_barrier = 0;          // reset persistent-kernel barrier

    float xv = x[i];
    float acc[64];
#pragma unroll
    for (int j = 0; j < 64; j++) acc[j] = sB2[j];
#pragma unroll
    for (int j1 = 0; j1 < 32; j1++) {
        float h = fmaxf(fmaf(xv, sW1[j1], sB1[j1]), 0.0f);
        const float4* w2r = reinterpret_cast<const float4*>(&sW2[j1 * 64]);
#pragma unroll
        for (int j = 0; j < 16; j++) {
            float4 w = w2r[j];
            acc[4*j+0] = fmaf(h, w.x, acc[4*j+0]);
            acc[4*j+1] = fmaf(h, w.y, acc[4*j+1]);
            acc[4*j+2] = fmaf(h, w.z, acc[4*j+2]);
            acc[4*j+3] = fmaf(h, w.w, acc[4*j+3]);
        }
    }
    float s = 0.0f;
#pragma unroll
    for (int j = 0; j < 64; j++) s = fmaf(fmaxf(acc[j], 0.0f), sWfc[j], s);

    g_s[i] = s;
}

// ---- single-pass decoupled-lookback scan + finalize + hop-0 seed -------------
__global__ void __launch_bounds__(SCANB) k_scan(const float* __restrict__ temp, int N, int E)
{
    __shared__ int sh[SCANB];
    __shared__ int sPrefix;
    const int tid = threadIdx.x;
    const int bid = blockIdx.x;
    const int i   = bid * SCANB + tid;

    int v = (i < N) ? g_deg[i] : 0;
    sh[tid] = v;
    __syncthreads();
#pragma unroll
    for (int d = 1; d < SCANB; d <<= 1) {
        int t = (tid >= d) ? sh[tid - d] : 0;
        __syncthreads();
        sh[tid] += t;
        __syncthreads();
    }
    int incl = sh[tid];

    int base   = bid * SCANB;
    int nvalid = N - base; if (nvalid > SCANB) nvalid = SCANB; if (nvalid < 0) nvalid = 0;
    if (tid == 0) {
        int agg = nvalid ? sh[nvalid - 1] : 0;
        if (bid == 0) {
            atomicExch(&g_lb[0], (2ull << 32) | (unsigned)agg);
            sPrefix = 0;
        } else {
            atomicExch(&g_lb[bid], (1ull << 32) | (unsigned)agg);
            unsigned long long sum = 0;
            int j = bid - 1;
            for (;;) {
                unsigned long long st;
                do { st = atomicAdd(&g_lb[j], 0ull); if (!(st >> 32)) __nanosleep(32); } while (!(st >> 32));
                sum += (unsigned)st;
                if ((st >> 32) == 2ull) break;
                j--;
            }
            atomicExch(&g_lb[bid], (2ull << 32) | (unsigned)(sum + agg));
            sPrefix = (int)sum;
        }
    }
    __syncthreads();

    if (i >= N) return;
    int val = incl - v + sPrefix;
    g_off[i]    = val;
    g_cursor[i] = val;
    if (i == 0) g_off[N] = E;

    float d = rsqrtf((float)(g_deg[i] + 1));   // +1 self-loop
    g_deg[i] = 0;                               // restore zero-entry invariant
    float s = g_s[i];
    float w = d * s;
    g_dinv[i]   = d;
    g_hidden[i] = temp[0] * s;
    g_curwA[i]  = w;
    g_hA[i]     = __float2half(w);
}

// ---- scatter edges into CSC order (stores BYTE offsets 2*row) ----------------
__global__ void __launch_bounds__(EBLK) k_scatter_vec(const int* __restrict__ row,
                                                      const int* __restrict__ col,
                                                      int E4, int rem)
{
    int t = blockIdx.x * blockDim.x + threadIdx.x;
    if (t < E4) {
        int4 r4 = reinterpret_cast<const int4*>(row)[t];
        int4 c4 = reinterpret_cast<const int4*>(col)[t];
        g_srow[atomicAdd(&g_cursor[c4.x], 1)] = r4.x << 1;
        g_srow[atomicAdd(&g_cursor[c4.y], 1)] = r4.y << 1;
        g_srow[atomicAdd(&g_cursor[c4.z], 1)] = r4.z << 1;
        g_srow[atomicAdd(&g_cursor[c4.w], 1)] = r4.w << 1;
    } else if (t - E4 < rem) {
        int e = 4 * E4 + (t - E4);
        g_srow[atomicAdd(&g_cursor[col[e]], 1)] = row[e] << 1;
    }
}
__global__ void __launch_bounds__(EBLK) k_scatter_sca(const int* __restrict__ row,
                                                      const int* __restrict__ col, int E)
{
    int e = blockIdx.x * blockDim.x + threadIdx.x;
    if (e < E) g_srow[atomicAdd(&g_cursor[col[e]], 1)] = row[e] << 1;
}

// ---- persistent propagation: multicast TMA-filled smem-gather hops -----------
__global__ void __launch_bounds__(PTHR, 1) __cluster_dims__(2, 1, 1)
k_prop(const float* __restrict__ temp,
       const float* __restrict__ bfc,
       float* __restrict__ out,
       int N, int K)
{
    extern __shared__ __align__(16) unsigned char smem_raw[];
    uint32_t smb;
    asm("{ .reg .u64 t; cvta.to.shared.u64 t, %1; cvt.u32.u64 %0, t; }"
        : "=r"(smb) : "l"(smem_raw));
    const uint32_t mbar = smb + SMEMB;

    uint32_t rank;
    asm("mov.u32 %0, %%cluster_ctarank;" : "=r"(rank));

    const int tid    = threadIdx.x;
    const int nwarps = gridDim.x * (PTHR / 32);
    const int gw     = blockIdx.x * (PTHR / 32) + (tid >> 5);
    const int lane   = tid & 31;

    if (tid == 0)
        asm volatile("mbarrier.init.shared.b64 [%0], 1;" :: "r"(mbar) : "memory");
    __syncthreads();
    // cluster sync: peer's mbarrier must be initialized before any multicast
    asm volatile("barrier.cluster.arrive.aligned;" ::: "memory");
    asm volatile("barrier.cluster.wait.aligned;"   ::: "memory");

    // each warp owns a contiguous chunk of <=32 nodes; lane -> node (registers)
    const int npw    = (N + nwarps - 1) / nwarps;
    const int nodeLo = gw * npw;
    const int nodeHi = (nodeLo + npw < N) ? (nodeLo + npw) : N;
    const int cnt    = (nodeHi > nodeLo) ? (nodeHi - nodeLo) : 0;
    const int idx    = nodeLo + lane;
    const bool act   = (lane < cnt);

    int   myStart = act ? __ldg(&g_off[idx])     : 0;
    int   myNext  = act ? __ldg(&g_off[idx + 1]) : 0;
    float myDinv  = act ? g_dinv[idx]            : 0.0f;
    float myHid   = act ? g_hidden[idx]          : 0.0f;
    float mySelf  = act ? g_curwA[idx]           : 0.0f;

    unsigned target = 0;

    for (int k = 1; k <= K; k++) {
        const float gamma = __ldg(&temp[k]);
        const bool  last  = (k == K);
        const char* srcG  = (k & 1) ? (const char*)g_hA : (const char*)g_hB;
        __half*     dstH  = (k & 1) ? g_hB : g_hA;
        const unsigned ph = (unsigned)((k - 1) & 1);

        // cooperative-slice multicast fill: CTA r loads bytes [r*HALFB, (r+1)*HALFB)
        // and multicasts to both cluster CTAs; mbarrier expects the FULL array.
        if (tid == 0) {
            asm volatile("mbarrier.arrive.expect_tx.shared.b64 _, [%0], %1;"
                         :: "r"(mbar), "r"((unsigned)SMEMB) : "memory");
            asm volatile("cp.async.bulk.shared::cluster.global"
                         ".mbarrier::complete_tx::bytes.multicast::cluster "
                         "[%0], [%1], %2, [%3], %4;"
                         :: "r"(smb + rank * HALFB), "l"(srcG + rank * HALFB),
                            "r"((unsigned)HALFB), "r"(mbar), "h"((uint16_t)0x3)
                         : "memory");
        }
        {   // all threads wait for fill completion (parity ph)
            unsigned done;
            asm volatile("{\n\t.reg .pred p;\n\t"
                         "mbarrier.try_wait.parity.shared.b64 p, [%1], %2;\n\t"
                         "selp.b32 %0, 1, 0, p;\n\t}"
                         : "=r"(done) : "r"(mbar), "r"(ph) : "memory");
            while (!done) {
                __nanosleep(32);
                asm volatile("{\n\t.reg .pred p;\n\t"
                             "mbarrier.try_wait.parity.shared.b64 p, [%1], %2;\n\t"
                             "selp.b32 %0, 1, 0, p;\n\t}"
                             : "=r"(done) : "r"(mbar), "r"(ph) : "memory");
            }
        }
        __syncthreads();

        // paired full-width smem gathers (srow holds byte offsets)
        float mySum = 0.0f;
        for (int j = 0; j < cnt; j += 2) {
            int s0 = __shfl_sync(0xFFFFFFFFu, myStart, j);
            int e0 = __shfl_sync(0xFFFFFFFFu, myNext,  j);
            int j1 = (j + 1 < cnt) ? (j + 1) : j;
            int s1 = __shfl_sync(0xFFFFFFFFu, myStart, j1);
            int e1 = __shfl_sync(0xFFFFFFFFu, myNext,  j1);
            if (j + 1 >= cnt) { s1 = 0; e1 = 0; }

            float sum0 = 0.0f, sum1 = 0.0f;
            int   t0 = s0 + lane, t1 = s1 + lane;
            while (t0 < e0 || t1 < e1) {
                float v0 = 0.0f, v1 = 0.0f;
                if (t0 < e0)
                    v0 = __half2float(*reinterpret_cast<const __half*>(
                             smem_raw + __ldg(&g_srow[t0])));
                if (t1 < e1)
                    v1 = __half2float(*reinterpret_cast<const __half*>(
                             smem_raw + __ldg(&g_srow[t1])));
                sum0 += v0; sum1 += v1;
                t0 += 32;  t1 += 32;
            }
#pragma unroll
            for (int d = 16; d > 0; d >>= 1) {
                sum0 += __shfl_xor_sync(0xFFFFFFFFu, sum0, d);
                sum1 += __shfl_xor_sync(0xFFFFFFFFu, sum1, d);
            }
            if (lane == j)     mySum = sum0;
            if (lane == j + 1) mySum = sum1;
        }

        float cur = myDinv * (mySelf + mySum);
        myHid  = fmaf(gamma, cur, myHid);
        mySelf = myDinv * cur;

        if (!last) {
            if (act) dstH[idx] = __float2half(mySelf);   // coalesced 2B
            __syncthreads();
            if (tid == 0) {
                __threadfence();                          // release (+IVALL)
                atomicAdd(&g_barrier, 1u);
                target += gridDim.x;
                while (*(volatile unsigned*)&g_barrier < target)
                    __nanosleep(32);
                __threadfence();                          // acquire (+IVALL)
            }
            __syncthreads();
        }
    }

    if (act) out[idx] = myHid + __ldg(&bfc[0]);

    // cluster exit hygiene
    asm volatile("barrier.cluster.arrive.aligned;" ::: "memory");
    asm volatile("barrier.cluster.wait.aligned;"   ::: "memory");
}

// ---------------------------------------------------------------------------
extern "C" void kernel_launch(void* const* d_in, const int* in_sizes, int n_in,
                              void* d_out, int out_size)
{
    const float* x    = (const float*)d_in[0];
    const int*   ei   = (const int*)  d_in[1];
    const float* W1   = (const float*)d_in[2];
    const float* b1   = (const float*)d_in[3];
    const float* W2   = (const float*)d_in[4];
    const float* b2   = (const float*)d_in[5];
    const float* temp = (const float*)d_in[6];
    const float* Wfc  = (const float*)d_in[7];
    const float* bfc  = (const float*)d_in[8];
    float*       out  = (float*)d_out;

    int N = in_sizes[0];
    int E = in_sizes[1] / 2;
    int K = in_sizes[6] - 1;

    const int* row = ei;
    const int* col = ei + E;

    int nb    = (N + NBLK - 1) / NBLK;
    int nscan = (N + SCANB - 1) / SCANB;   // 98 (<128: lookback table safe)

    bool vec_ok = (E % 4 == 0);
    int  E4 = E >> 2, rem = E & 3;
    int  eb_vec = (E4 + rem + EBLK - 1) / EBLK;
    int  eb_sca = (E + EBLK - 1) / EBLK;

    int dev = 0, sms = 0;
    cudaGetDevice(&dev);
    cudaDeviceGetAttribute(&sms, cudaDevAttrMultiProcessorCount, dev);
    if (sms <= 0) sms = 148;

    // persistent cluster grid: even block count, 2 SMs of slack so all
    // clusters are resident under ANY die split -> grid barrier is safe
    int pb = (sms >= 8) ? (sms - 2) : sms;
    pb &= ~1;

    static int attr_done = 0;
    if (!attr_done) {
        cudaFuncSetAttribute(k_prop, cudaFuncAttributeMaxDynamicSharedMemorySize, SMEMT);
        attr_done = 1;
    }

    if (vec_ok) {
        k_mlp_hist<<<nb + eb_vec, NBLK>>>(x, W1, b1, W2, b2, Wfc, col, N, nb, E4, rem);
    } else {
        k_mlp_hist<<<nb + eb_sca, NBLK>>>(x, W1, b1, W2, b2, Wfc, col, N, nb, 0, E);
    }
    k_scan<<<nscan, SCANB>>>(temp, N, E);
    if (vec_ok) k_scatter_vec<<<eb_vec, EBLK>>>(row, col, E4, rem);
    else        k_scatter_sca<<<eb_sca, EBLK>>>(row, col, E);

    k_prop<<<pb, PTHR, SMEMT>>>(temp, bfc, out, N, K);
}

// round 14
// speedup vs baseline: 1.1918x; 1.1918x over previous
#include <cuda_runtime.h>
#include <cuda_fp16.h>
#include <stdint.h>

// ---------------------------------------------------------------------------
// GPRNet: out = sum_k temp[k] * A_hat^k (MLP(x)@W_fc) + b_fc  (scalar per node)
// 4 launches:
//  1) k_mlp_hist_fill: MLP (g_s) || col histogram (g_deg) || pad-fill g_srow
//  2) k_scan: chunk-max lookback scan -> chunk bases, per-node cursor, dinv,
//     hidden, fp32+fp16 hop-0 seeds; zeroes g_deg
//  3) k_scatter: transposed CSC scatter: slot = atomicAdd(cursor[c], 32)
//  4) k_prop: persistent, 1 blk/SM x 1024 thr, 196KB smem fp16 curw filled by
//     ONE cp.async.bulk per hop; NODE-PER-LANE gather (no shuffles, no
//     divergence, padded slots read a zero half); IVALL grid barrier.
// ---------------------------------------------------------------------------

#define MAXN    100352
#define MAXE    3276800
#define MAXPAD  8388608            // padded srow capacity (slots)
#define MAXCH   ((MAXN + 31) / 32) // max chunks
#define NBLK    256
#define EBLK    256
#define SCANB   1024
#define MAXSB   128
#define PTHR    1024
#define FILLB   1024               // pad-fill blocks in launch 1
#define SMEMB   (MAXN * 2)         // 200704 bytes fp16 curw
#define ZPAD    16                 // zero halves after curw
#define SMEMT   (SMEMB + ZPAD + 16)

__device__ int      g_deg[MAXN];           // zero at every call entry (invariant)
__device__ int      g_cursor[MAXN];        // slot cursor per node
__device__ int      g_chunkbase[MAXCH + 32];
__device__ int      g_chunkmax[MAXCH + 32];
__device__ int      g_srow[MAXPAD];        // BYTE offsets (2*row); pad -> SMEMB
__device__ float    g_dinv[MAXN];
__device__ float    g_s[MAXN];
__device__ float    g_hidden[MAXN];
__device__ float    g_curwA[MAXN];                       // fp32 self-term seed
__device__ __align__(16) __half g_hA[MAXN];              // fp16 ping
__device__ __align__(16) __half g_hB[MAXN];              // fp16 pong
__device__ unsigned g_barrier;
__device__ unsigned long long g_lb[MAXSB];               // lookback: flag<<32|val

// ---- launch 1: fused MLP + histogram + srow pad-fill -------------------------
__global__ void __launch_bounds__(NBLK) k_mlp_hist_fill(
    const float* __restrict__ x,
    const float* __restrict__ W1, const float* __restrict__ b1,
    const float* __restrict__ W2, const float* __restrict__ b2,
    const float* __restrict__ Wfc,
    const int* __restrict__ col,
    int N, int nbMlp, int nbHist, int E4, int rem)
{
    int b = (int)blockIdx.x;
    if (b >= nbMlp + nbHist) {
        // ---- pad-fill role: g_srow[*] = SMEMB (byte offset of zero half) ----
        int fb  = b - nbMlp - nbHist;
        int t   = fb * NBLK + threadIdx.x;
        int4* p = reinterpret_cast<int4*>(g_srow);
        int4  v = make_int4(SMEMB, SMEMB, SMEMB, SMEMB);
        for (int j = t; j < MAXPAD / 4; j += FILLB * NBLK) p[j] = v;
        return;
    }
    if (b >= nbMlp) {
        // ---- histogram role ----
        int hb = b - nbMlp;
        if (hb == 0 && threadIdx.x < MAXSB) g_lb[threadIdx.x] = 0ull;  // reset lookback
        int t = hb * NBLK + threadIdx.x;
        if (t < E4) {
            int4 c4 = reinterpret_cast<const int4*>(col)[t];
            atomicAdd(&g_deg[c4.x], 1);
            atomicAdd(&g_deg[c4.y], 1);
            atomicAdd(&g_deg[c4.z], 1);
            atomicAdd(&g_deg[c4.w], 1);
        } else if (t - E4 < rem) {
            atomicAdd(&g_deg[col[4 * E4 + (t - E4)]], 1);
        }
        return;
    }

    // ---- MLP role ----
    __shared__ float sW1[32], sB1[32], sB2[64], sWfc[64];
    __shared__ __align__(16) float sW2[2048];

    for (int t = threadIdx.x; t < 2048; t += blockDim.x) sW2[t] = W2[t];
    if (threadIdx.x < 32) { sW1[threadIdx.x] = W1[threadIdx.x]; sB1[threadIdx.x] = b1[threadIdx.x]; }
    if (threadIdx.x < 64) { sB2[threadIdx.x] = b2[threadIdx.x]; sWfc[threadIdx.x] = Wfc[threadIdx.x]; }
    __syncthreads();

    int i = b * NBLK + threadIdx.x;
    if (i >= N) return;
    if (i == 0) g_barrier = 0;          // reset persistent-kernel barrier

    float xv = x[i];
    float acc[64];
#pragma unroll
    for (int j = 0; j < 64; j++) acc[j] = sB2[j];
#pragma unroll
    for (int j1 = 0; j1 < 32; j1++) {
        float h = fmaxf(fmaf(xv, sW1[j1], sB1[j1]), 0.0f);
        const float4* w2r = reinterpret_cast<const float4*>(&sW2[j1 * 64]);
#pragma unroll
        for (int j = 0; j < 16; j++) {
            float4 w = w2r[j];
            acc[4*j+0] = fmaf(h, w.x, acc[4*j+0]);
            acc[4*j+1] = fmaf(h, w.y, acc[4*j+1]);
            acc[4*j+2] = fmaf(h, w.z, acc[4*j+2]);
            acc[4*j+3] = fmaf(h, w.w, acc[4*j+3]);
        }
    }
    float s = 0.0f;
#pragma unroll
    for (int j = 0; j < 64; j++) s = fmaf(fmaxf(acc[j], 0.0f), sWfc[j], s);

    g_s[i] = s;
}

// ---- launch 2: chunk-max lookback scan + finalize + hop-0 seed ---------------
__global__ void __launch_bounds__(SCANB) k_scan(const float* __restrict__ temp, int N)
{
    __shared__ int cm[32];      // chunk maxes (32 chunks per block)
    __shared__ int cpre[32];    // exclusive prefix of chunk maxes
    __shared__ int sPrefix;     // sum of prior blocks' chunk-max totals
    const int tid  = threadIdx.x;
    const int bid  = blockIdx.x;
    const int lane = tid & 31;
    const int w    = tid >> 5;
    const int i    = bid * SCANB + tid;

    int v = (i < N) ? g_deg[i] : 0;

    // warp max -> chunk max
    int m = v;
#pragma unroll
    for (int d = 16; d > 0; d >>= 1) {
        int t = __shfl_xor_sync(0xFFFFFFFFu, m, d);
        m = (t > m) ? t : m;
    }
    if (lane == 0) cm[w] = m;
    __syncthreads();

    // warp 0: inclusive scan of 32 chunk maxes + lookback
    if (tid < 32) {
        int c   = cm[tid];
        int inc = c;
#pragma unroll
        for (int d = 1; d < 32; d <<= 1) {
            int t = __shfl_up_sync(0xFFFFFFFFu, inc, d);
            if (tid >= d) inc += t;
        }
        cpre[tid] = inc - c;
        if (tid == 31) {
            int agg = inc;       // block total of chunk maxes
            if (bid == 0) {
                atomicExch(&g_lb[0], (2ull << 32) | (unsigned)agg);
                sPrefix = 0;
            } else {
                atomicExch(&g_lb[bid], (1ull << 32) | (unsigned)agg);
                unsigned long long sum = 0;
                int j = bid - 1;
                for (;;) {
                    unsigned long long st;
                    do { st = atomicAdd(&g_lb[j], 0ull); if (!(st >> 32)) __nanosleep(32); } while (!(st >> 32));
                    sum += (unsigned)st;
                    if ((st >> 32) == 2ull) break;
                    j--;
                }
                atomicExch(&g_lb[bid], (2ull << 32) | (unsigned)(sum + agg));
                sPrefix = (int)sum;
            }
        }
    }
    __syncthreads();

    if (i >= N) return;
    int chunkBase = 32 * (sPrefix + cpre[w]);     // slot index
    if (lane == 0) {
        g_chunkbase[bid * 32 + w] = chunkBase;
        g_chunkmax [bid * 32 + w] = cm[w];
    }
    g_cursor[i] = chunkBase + lane;               // scatter: +=32 per edge

    float d = rsqrtf((float)(v + 1));             // +1 self-loop
    g_deg[i] = 0;                                 // restore zero-entry invariant
    float s = g_s[i];
    float wv = d * s;
    g_dinv[i]   = d;
    g_hidden[i] = temp[0] * s;
    g_curwA[i]  = wv;
    g_hA[i]     = __float2half(wv);
}

// ---- launch 3: transposed CSC scatter (values = BYTE offsets 2*row) ----------
__global__ void __launch_bounds__(EBLK) k_scatter_vec(const int* __restrict__ row,
                                                      const int* __restrict__ col,
                                                      int E4, int rem)
{
    int t = blockIdx.x * blockDim.x + threadIdx.x;
    if (t < E4) {
        int4 r4 = reinterpret_cast<const int4*>(row)[t];
        int4 c4 = reinterpret_cast<const int4*>(col)[t];
        g_srow[atomicAdd(&g_cursor[c4.x], 32)] = r4.x << 1;
        g_srow[atomicAdd(&g_cursor[c4.y], 32)] = r4.y << 1;
        g_srow[atomicAdd(&g_cursor[c4.z], 32)] = r4.z << 1;
        g_srow[atomicAdd(&g_cursor[c4.w], 32)] = r4.w << 1;
    } else if (t - E4 < rem) {
        int e = 4 * E4 + (t - E4);
        g_srow[atomicAdd(&g_cursor[col[e]], 32)] = row[e] << 1;
    }
}
__global__ void __launch_bounds__(EBLK) k_scatter_sca(const int* __restrict__ row,
                                                      const int* __restrict__ col, int E)
{
    int e = blockIdx.x * blockDim.x + threadIdx.x;
    if (e < E) g_srow[atomicAdd(&g_cursor[col[e]], 32)] = row[e] << 1;
}

// ---- launch 4: persistent propagation, node-per-lane smem gather -------------
__global__ void __launch_bounds__(PTHR, 1) k_prop(const float* __restrict__ temp,
                                                  const float* __restrict__ bfc,
                                                  float* __restrict__ out,
                                                  int N, int K, int nChunks)
{
    extern __shared__ __align__(16) unsigned char smem_raw[];
    uint32_t smb;
    asm("{ .reg .u64 t; cvta.to.shared.u64 t, %1; cvt.u32.u64 %0, t; }"
        : "=r"(smb) : "l"(smem_raw));
    const uint32_t mbar = smb + SMEMB + ZPAD;

    const int tid  = threadIdx.x;
    const int lane = tid & 31;
    const int gw   = blockIdx.x * (PTHR / 32) + (tid >> 5);

    // zero halves at [SMEMB, SMEMB+ZPAD): target of all padding slots
    if (tid < ZPAD / 2) reinterpret_cast<__half*>(smem_raw + SMEMB)[tid] = __float2half(0.0f);
    if (tid == 0)
        asm volatile("mbarrier.init.shared.b64 [%0], 1;" :: "r"(mbar) : "memory");
    __syncthreads();

    const bool actC = (gw < nChunks);
    const int  idx  = gw * 32 + lane;
    const bool actN = actC && (idx < N);

    const int  base = actC ? __ldg(&g_chunkbase[gw]) : 0;
    const int  cmax = actC ? __ldg(&g_chunkmax[gw])  : 0;

    float myDinv = actN ? g_dinv[idx]   : 0.0f;
    float myHid  = actN ? g_hidden[idx] : 0.0f;
    float mySelf = actN ? g_curwA[idx]  : 0.0f;

    unsigned target = 0;

    for (int k = 1; k <= K; k++) {
        const float gamma = __ldg(&temp[k]);
        const bool  last  = (k == K);
        const char* srcG  = (k & 1) ? (const char*)g_hA : (const char*)g_hB;
        __half*     dstH  = (k & 1) ? g_hB : g_hA;
        const unsigned ph = (unsigned)((k - 1) & 1);

        // ONE bulk TMA fill of the whole fp16 curw array (plain, per-CTA)
        if (tid == 0) {
            asm volatile("mbarrier.arrive.expect_tx.shared.b64 _, [%0], %1;"
                         :: "r"(mbar), "r"((unsigned)SMEMB) : "memory");
            asm volatile("cp.async.bulk.shared::cluster.global.mbarrier::complete_tx::bytes "
                         "[%0], [%1], %2, [%3];"
                         :: "r"(smb), "l"(srcG), "r"((unsigned)SMEMB), "r"(mbar) : "memory");
        }
        {
            unsigned done;
            asm volatile("{\n\t.reg .pred p;\n\t"
                         "mbarrier.try_wait.parity.shared.b64 p, [%1], %2;\n\t"
                         "selp.b32 %0, 1, 0, p;\n\t}"
                         : "=r"(done) : "r"(mbar), "r"(ph) : "memory");
            while (!done) {
                __nanosleep(32);
                asm volatile("{\n\t.reg .pred p;\n\t"
                             "mbarrier.try_wait.parity.shared.b64 p, [%1], %2;\n\t"
                             "selp.b32 %0, 1, 0, p;\n\t}"
                             : "=r"(done) : "r"(mbar), "r"(ph) : "memory");
            }
        }
        __syncthreads();

        // node-per-lane gather: no shuffles, no divergence (padding reads 0)
        float s0 = 0.0f, s1 = 0.0f, s2 = 0.0f, s3 = 0.0f;
        const int* sp = g_srow + base + lane;
        int i = 0;
        for (; i + 4 <= cmax; i += 4) {
            int o0 = __ldg(sp);
            int o1 = __ldg(sp + 32);
            int o2 = __ldg(sp + 64);
            int o3 = __ldg(sp + 96);
            s0 += __half2float(*reinterpret_cast<const __half*>(smem_raw + o0));
            s1 += __half2float(*reinterpret_cast<const __half*>(smem_raw + o1));
            s2 += __half2float(*reinterpret_cast<const __half*>(smem_raw + o2));
            s3 += __half2float(*reinterpret_cast<const __half*>(smem_raw + o3));
            sp += 128;
        }
        for (; i < cmax; i++) {
            s0 += __half2float(*reinterpret_cast<const __half*>(smem_raw + __ldg(sp)));
            sp += 32;
        }
        float mySum = (s0 + s1) + (s2 + s3);

        float cur = myDinv * (mySelf + mySum);
        myHid  = fmaf(gamma, cur, myHid);
        mySelf = myDinv * cur;

        if (!last) {
            if (actN) dstH[idx] = __float2half(mySelf);   // coalesced 2B
            __syncthreads();
            if (tid == 0) {
                __threadfence();                          // release (+IVALL)
                atomicAdd(&g_barrier, 1u);
                target += gridDim.x;
                while (*(volatile unsigned*)&g_barrier < target)
                    __nanosleep(32);
                __threadfence();                          // acquire (+IVALL)
            }
            __syncthreads();
        }
    }

    if (actN) out[idx] = myHid + __ldg(&bfc[0]);
}

// ---------------------------------------------------------------------------
extern "C" void kernel_launch(void* const* d_in, const int* in_sizes, int n_in,
                              void* d_out, int out_size)
{
    const float* x    = (const float*)d_in[0];
    const int*   ei   = (const int*)  d_in[1];
    const float* W1   = (const float*)d_in[2];
    const float* b1   = (const float*)d_in[3];
    const float* W2   = (const float*)d_in[4];
    const float* b2   = (const float*)d_in[5];
    const float* temp = (const float*)d_in[6];
    const float* Wfc  = (const float*)d_in[7];
    const float* bfc  = (const float*)d_in[8];
    float*       out  = (float*)d_out;

    int N = in_sizes[0];
    int E = in_sizes[1] / 2;
    int K = in_sizes[6] - 1;

    const int* row = ei;
    const int* col = ei + E;

    int nb      = (N + NBLK - 1) / NBLK;
    int nscan   = (N + SCANB - 1) / SCANB;     // 98 (<128: lookback table ok)
    int nChunks = (N + 31) / 32;

    bool vec_ok = (E % 4 == 0);
    int  E4 = E >> 2, rem = E & 3;
    int  eb_vec = (E4 + rem + EBLK - 1) / EBLK;
    int  eb_sca = (E + EBLK - 1) / EBLK;
    int  ebh    = vec_ok ? eb_vec : eb_sca;

    int dev = 0, sms = 0;
    cudaGetDevice(&dev);
    cudaDeviceGetAttribute(&sms, cudaDevAttrMultiProcessorCount, dev);
    if (sms <= 0) sms = 148;

    int pb = sms - 2;                           // persistent grid (resident)
    if (pb * 32 < nChunks) pb = (nChunks + 31) / 32;

    static int attr_done = 0;
    if (!attr_done) {
        cudaFuncSetAttribute(k_prop, cudaFuncAttributeMaxDynamicSharedMemorySize, SMEMT);
        attr_done = 1;
    }

    if (vec_ok)
        k_mlp_hist_fill<<<nb + ebh + FILLB, NBLK>>>(x, W1, b1, W2, b2, Wfc, col,
                                                    N, nb, ebh, E4, rem);
    else
        k_mlp_hist_fill<<<nb + ebh + FILLB, NBLK>>>(x, W1, b1, W2, b2, Wfc, col,
                                                    N, nb, ebh, 0, E);
    k_scan<<<nscan, SCANB>>>(temp, N);
    if (vec_ok) k_scatter_vec<<<eb_vec, EBLK>>>(row, col, E4, rem);
    else        k_scatter_sca<<<eb_sca, EBLK>>>(row, col, E);

    k_prop<<<pb, PTHR, SMEMT>>>(temp, bfc, out, N, K, nChunks);
}